// round 4
// baseline (speedup 1.0000x reference)
#include <cuda_runtime.h>
#include <cstdint>

#define FULLMASK 0xffffffffu
using ull = unsigned long long;

constexpr int NN = 22;
constexpr int D  = 64;

__device__ __align__(16) float g_M1[576];   // M1[(s*3+t)*64 + d] = W[s] @ a[t,:64]
__device__ __align__(16) float g_w2[192];   // w2[t*64 + d]       = W[t] @ a[t,64:]
__device__ int g_mflag;                      // 1 => mask is uint8, 0 => int32

__device__ __forceinline__ ull fma2(ull a, ull b, ull c) {
    ull d;
    asm("fma.rn.f32x2 %0, %1, %2, %3;" : "=l"(d) : "l"(a), "l"(b), "l"(c));
    return d;
}
__device__ __forceinline__ ull pack2(float v) {
    ull r;
    asm("mov.b64 %0, {%1, %1};" : "=l"(r) : "f"(v));
    return r;
}
__device__ __forceinline__ float lo32(ull v){ return __uint_as_float((unsigned)v); }
__device__ __forceinline__ float hi32(ull v){ return __uint_as_float((unsigned)(v >> 32)); }

// ================= prep kernel: 1 block, 256 threads =================
__global__ void hetgat_prep(const float* __restrict__ W, const float* __restrict__ a,
                            const void* __restrict__ maskp)
{
    const int tid = threadIdx.x;
    if (tid == 0) {
        const int* mi = (const int*)maskp;
        int bad = 0;
        #pragma unroll 8
        for (int i = 0; i < 64; ++i) bad |= ((unsigned)__ldg(mi + i) > 1u);
        g_mflag = bad;
    }
    for (int idx = tid; idx < 768; idx += 256) {
        if (idx < 576) {
            int s = idx / 192; int r = idx - s*192; int t = r >> 6; int d = r & 63;
            const float* wr = W + (s*D + d)*D;
            const float* av = a + t*128;
            float a0=0.f,a1=0.f,a2=0.f,a3=0.f;
            #pragma unroll
            for (int k = 0; k < D; k += 4) {
                a0 += __ldg(wr+k+0)*__ldg(av+k+0);
                a1 += __ldg(wr+k+1)*__ldg(av+k+1);
                a2 += __ldg(wr+k+2)*__ldg(av+k+2);
                a3 += __ldg(wr+k+3)*__ldg(av+k+3);
            }
            g_M1[(s*3 + t)*64 + d] = (a0+a1)+(a2+a3);
        } else {
            int r = idx - 576; int t = r >> 6; int d = r & 63;
            const float* wr = W + (t*D + d)*D;
            const float* av = a + t*128 + 64;
            float a0=0.f,a1=0.f,a2=0.f,a3=0.f;
            #pragma unroll
            for (int k = 0; k < D; k += 4) {
                a0 += __ldg(wr+k+0)*__ldg(av+k+0);
                a1 += __ldg(wr+k+1)*__ldg(av+k+1);
                a2 += __ldg(wr+k+2)*__ldg(av+k+2);
                a3 += __ldg(wr+k+3)*__ldg(av+k+3);
            }
            g_w2[t*64 + d] = (a0+a1)+(a2+a3);
        }
    }
}

// ================= main kernel: 128 threads, 2 batches/warp, 512 blocks =================
__global__ __launch_bounds__(128, 4) void hetgat_main(
    const float* __restrict__ h,      // (B, 22, 64)
    const void*  __restrict__ maskp,  // (3, B, 22)
    const float* __restrict__ W,      // (3, 64, 64) = rows k=t*64+d, h contiguous
    float* __restrict__ out,          // (B, 64)
    int B)
{
    __shared__ __align__(16) float s_c[4][96];       // per-warp coeffs c[t*32+node]
    __shared__ __align__(16) float s_g[4][2][192];   // per-warp, per-jb g[k]

    const int tid  = threadIdx.x;
    const int wid  = tid >> 5;
    const int lane = tid & 31;

    const bool u8m = (__ldg(&g_mflag) != 0);
    const int* mi32 = (const int*)maskp;
    const uint8_t* mu8 = (const uint8_t*)maskp;
    const size_t mT = (size_t)B * NN;

    // hoisted lane slices (batch-independent): lane owns d = 2*lane, 2*lane+1
    float w2x[3], w2y[3];
    #pragma unroll
    for (int t = 0; t < 3; ++t) {
        float2 v = __ldg(((const float2*)(g_w2 + t*64)) + lane);
        w2x[t] = v.x; w2y[t] = v.y;
    }
    float m1x[9], m1y[9];
    #pragma unroll
    for (int v = 0; v < 9; ++v) {
        float2 m = __ldg(((const float2*)(g_M1 + v*64)) + lane);
        m1x[v] = m.x; m1y[v] = m.y;
    }

    // per-lane pair mapping
    const int tA = lane / 10;            // 3 for lanes 30,31 (unused)
    const int nA = 1 + (lane - tA*10);
    const bool validA = (lane < 30);
    const int tO = lane / 11;
    const int nO = 11 + (lane - tO*11);

    const int bbase = blockIdx.x * 8 + wid * 2;

    #pragma unroll
    for (int jb = 0; jb < 2; ++jb) {
        const int b = bbase + jb;
        if (b < B) {   // warp-uniform
            const size_t boff = (size_t)b * NN;
            auto mld = [&](int t, int node) -> int {
                size_t i = (size_t)t * mT + boff + node;
                return u8m ? (int)mu8[i] : mi32[i];
            };
            // ---- prefetch masks (latency overlap with dots) ----
            int mAv = 1, mOv, mEv = 1, mSv = 0;
            if (validA)   mAv = mld(tA, nA);
            mOv = mld(tO, nO);
            if (lane == 30) mEv = mld(2, 21);
            if (lane < 3)   mSv = mld(lane, 0);

            // ---- load h ----
            const float2* hb = (const float2*)(h + (size_t)b * (NN*D));
            float hx[NN], hy[NN];
            #pragma unroll
            for (int n = 0; n < NN; ++n) {
                float2 v = hb[n*32 + lane];
                hx[n] = v.x; hy[n] = v.y;
            }

            // ======== PASS 1: ally dots (30) + opp pair (2,node21) in slot 30 ========
            float p[32];
            #pragma unroll
            for (int v = 0; v < 30; ++v) {
                int t = v / 10, n = 1 + v % 10;
                p[v] = fmaf(hy[n], w2y[t], hx[n] * w2x[t]);
            }
            p[30] = fmaf(hy[21], w2y[2], hx[21] * w2x[2]);
            p[31] = 0.f;
            #pragma unroll
            for (int sh = 16; sh >= 1; sh >>= 1) {
                bool up = (lane & sh) != 0;
                #pragma unroll
                for (int k = 0; k < sh; ++k) {
                    float send = up ? p[k] : p[k + sh];
                    float recv = __shfl_xor_sync(FULLMASK, send, sh);
                    float keep = up ? p[k + sh] : p[k];
                    p[k] = keep + recv;
                }
            }
            const float dA = p[0];   // lane v: ally dot v (lane30: opp(2,21))

            // ======== PASS 2: opp dots oi=0..31 ========
            #pragma unroll
            for (int v = 0; v < 32; ++v) {
                int t = v / 11, n = 11 + v % 11;
                p[v] = fmaf(hy[n], w2y[t], hx[n] * w2x[t]);
            }
            #pragma unroll
            for (int sh = 16; sh >= 1; sh >>= 1) {
                bool up = (lane & sh) != 0;
                #pragma unroll
                for (int k = 0; k < sh; ++k) {
                    float send = up ? p[k] : p[k + sh];
                    float recv = __shfl_xor_sync(FULLMASK, send, sh);
                    float keep = up ? p[k + sh] : p[k];
                    p[k] = keep + recv;
                }
            }
            const float dO = p[0];   // lane oi: opp dot oi

            // ======== PASS 3: self dots st[s*3+t] (9 in 16 slots) ========
            float q[16];
            #pragma unroll
            for (int v = 0; v < 9; ++v)
                q[v] = fmaf(hy[0], m1y[v], hx[0] * m1x[v]);
            #pragma unroll
            for (int v = 9; v < 16; ++v) q[v] = 0.f;
            #pragma unroll
            for (int sh = 8; sh >= 1; sh >>= 1) {
                bool up = (lane & sh) != 0;
                #pragma unroll
                for (int k = 0; k < sh; ++k) {
                    float send = up ? q[k] : q[k + sh];
                    float recv = __shfl_xor_sync(FULLMASK, send, sh);
                    float keep = up ? q[k + sh] : q[k];
                    q[k] = keep + recv;
                }
            }
            q[0] += __shfl_xor_sync(FULLMASK, q[0], 16);
            const float dX = q[0];   // lanes 0-8 hold st[s*3+t]

            // ======== softmax (no max-subtraction; shift-invariant, |e|<~12) ========
            float s0A = __shfl_sync(FULLMASK, dX, tA);
            float s1A = __shfl_sync(FULLMASK, dX, 3 + tA);
            float s2A = __shfl_sync(FULLMASK, dX, 6 + tA);
            float s0O = __shfl_sync(FULLMASK, dX, tO);
            float s1O = __shfl_sync(FULLMASK, dX, 3 + tO);
            float s2O = __shfl_sync(FULLMASK, dX, 6 + tO);

            float lsA = 0.f;
            if (validA && mAv == 0)
                lsA = __expf(s0A + dA) + __expf(s1A + dA) + __expf(s2A + dA);
            float lsO = 0.f;
            if (mOv == 0)
                lsO = __expf(s0O + dO) + __expf(s1O + dO) + __expf(s2O + dO);
            float lsE = 0.f;
            if (lane == 30 && mEv == 0)   // extra opp pair (t=2, node=21); lane30 tO==2
                lsE = __expf(s0O + dA) + __expf(s1O + dA) + __expf(s2O + dA);

            float SA = lsA, SO = lsO + lsE;
            #pragma unroll
            for (int off = 16; off > 0; off >>= 1) {
                SA += __shfl_xor_sync(FULLMASK, SA, off);
                SO += __shfl_xor_sync(FULLMASK, SO, off);
            }

            if (validA) s_c[wid][tA*32 + nA] = (mAv == 0) ? __fdividef(lsA, SA) : 0.f;
            s_c[wid][tO*32 + nO] = (mOv == 0) ? __fdividef(lsO, SO) : 0.f;
            if (lane == 30) s_c[wid][2*32 + 21] = (mEv == 0) ? __fdividef(lsE, SO) : 0.f;
            if (lane < 3)   s_c[wid][lane*32 + 0] = mSv ? 1.0f : 0.0f;
            __syncwarp();

            // ======== combine: g[t][d] = sum_n c[t][n]*h[n][d] ========
            float gx[3] = {0.f,0.f,0.f}, gy[3] = {0.f,0.f,0.f};
            const float4* scv = (const float4*)s_c[wid];
            #pragma unroll
            for (int t = 0; t < 3; ++t) {
                #pragma unroll
                for (int c4 = 0; c4 < 5; ++c4) {
                    float4 cq = scv[t*8 + c4];
                    int n0 = c4*4;
                    gx[t] = fmaf(cq.x, hx[n0+0], gx[t]); gy[t] = fmaf(cq.x, hy[n0+0], gy[t]);
                    gx[t] = fmaf(cq.y, hx[n0+1], gx[t]); gy[t] = fmaf(cq.y, hy[n0+1], gy[t]);
                    gx[t] = fmaf(cq.z, hx[n0+2], gx[t]); gy[t] = fmaf(cq.z, hy[n0+2], gy[t]);
                    gx[t] = fmaf(cq.w, hx[n0+3], gx[t]); gy[t] = fmaf(cq.w, hy[n0+3], gy[t]);
                }
                float4 cq = scv[t*8 + 5];   // nodes 20,21
                gx[t] = fmaf(cq.x, hx[20], gx[t]); gy[t] = fmaf(cq.x, hy[20], gy[t]);
                gx[t] = fmaf(cq.y, hx[21], gx[t]); gy[t] = fmaf(cq.y, hy[21], gy[t]);
            }
            #pragma unroll
            for (int t = 0; t < 3; ++t)
                ((float2*)(s_g[wid][jb] + t*64))[lane] = make_float2(gx[t], gy[t]);
            __syncwarp();
        }
    }

    // ======== final mat-vec: half-warp per batch, lane owns 4 h-columns ========
    // out[b][hh] = elu( sum_k g[k] * W[k][hh] ), W row k contiguous in hh.
    const int half = lane >> 4;          // 0 -> jb0, 1 -> jb1
    const int hl   = lane & 15;          // h columns hl*4 .. hl*4+3
    const float4* gsrc = (const float4*)s_g[wid][half];
    const ulonglong2* Wv = (const ulonglong2*)W;   // row k at index k*16, 4 floats/elem

    ull a0 = 0ull, a1 = 0ull;
    #pragma unroll 8
    for (int i = 0; i < 48; ++i) {       // k = 4i .. 4i+3
        float4 gv = gsrc[i];
        ulonglong2 w0 = __ldg(Wv + (4*i+0)*16 + hl);
        ulonglong2 w1 = __ldg(Wv + (4*i+1)*16 + hl);
        ulonglong2 w2 = __ldg(Wv + (4*i+2)*16 + hl);
        ulonglong2 w3 = __ldg(Wv + (4*i+3)*16 + hl);
        ull g0 = pack2(gv.x), g1 = pack2(gv.y), g2 = pack2(gv.z), g3 = pack2(gv.w);
        a0 = fma2(g0, w0.x, a0); a1 = fma2(g0, w0.y, a1);
        a0 = fma2(g1, w1.x, a0); a1 = fma2(g1, w1.y, a1);
        a0 = fma2(g2, w2.x, a0); a1 = fma2(g2, w2.y, a1);
        a0 = fma2(g3, w3.x, a0); a1 = fma2(g3, w3.y, a1);
    }

    const int bh = bbase + half;
    if (bh < B) {
        float r0 = lo32(a0), r1 = hi32(a0), r2 = lo32(a1), r3 = hi32(a1);
        float4 o;
        o.x = (r0 > 0.f) ? r0 : expm1f(r0);
        o.y = (r1 > 0.f) ? r1 : expm1f(r1);
        o.z = (r2 > 0.f) ? r2 : expm1f(r2);
        o.w = (r3 > 0.f) ? r3 : expm1f(r3);
        ((float4*)(out + (size_t)bh * D))[hl] = o;
    }
}

extern "C" void kernel_launch(void* const* d_in, const int* in_sizes, int n_in,
                              void* d_out, int out_size)
{
    const float* h = nullptr;
    const void* mask = nullptr;
    const float* W = nullptr;
    const float* a = nullptr;
    long hsz = 0; int hidx = -1;
    for (int i = 0; i < n_in; ++i) {
        if (in_sizes[i] == 12288)      W = (const float*)d_in[i];
        else if (in_sizes[i] == 384)   a = (const float*)d_in[i];
        if ((long)in_sizes[i] > hsz) { hsz = in_sizes[i]; hidx = i; }
    }
    h = (const float*)d_in[hidx];
    const int B = (int)(hsz / (NN * D));
    for (int i = 0; i < n_in; ++i) {
        if (i != hidx && (long)in_sizes[i] == (long)3 * B * NN)
            mask = d_in[i];
    }

    hetgat_prep<<<1, 256>>>(W, a, mask);
    dim3 grid((B + 7) / 8);   // 512 blocks for B=4096
    hetgat_main<<<grid, 128>>>(h, mask, W, (float*)d_out, B);
}

// round 5
// speedup vs baseline: 2.2395x; 2.2395x over previous
#include <cuda_runtime.h>
#include <cstdint>

#define FULLMASK 0xffffffffu
using ull = unsigned long long;

constexpr int NN = 22;
constexpr int D  = 64;

__device__ __align__(16) float g_M1[576];   // M1[(s*3+t)*64 + d] = sum_h W[s][d][h]*a[t][h]
__device__ __align__(16) float g_w2[192];   // w2[t*64 + d]       = sum_h W[t][d][h]*a[t][64+h]
__device__ int g_mflag;                      // 1 => mask is uint8, 0 => int32

__device__ __forceinline__ ull fma2(ull a, ull b, ull c) {
    ull d;
    asm("fma.rn.f32x2 %0, %1, %2, %3;" : "=l"(d) : "l"(a), "l"(b), "l"(c));
    return d;
}
__device__ __forceinline__ ull pack2(float v) {
    ull r;
    asm("mov.b64 %0, {%1, %1};" : "=l"(r) : "f"(v));
    return r;
}
__device__ __forceinline__ float lo32(ull v){ return __uint_as_float((unsigned)v); }
__device__ __forceinline__ float hi32(ull v){ return __uint_as_float((unsigned)(v >> 32)); }

// ================= prep kernel: 6 blocks x 128, one THREAD per output =================
__global__ __launch_bounds__(128) void hetgat_prep(
    const float* __restrict__ W, const float* __restrict__ a,
    const void* __restrict__ maskp)
{
    const int tid = threadIdx.x;
    const int idx = blockIdx.x * 128 + tid;

    // mask dtype autodetect: warp 0 of block 0, parallel (2 words/lane)
    if (blockIdx.x == 0 && tid < 32) {
        const int* mi = (const int*)maskp;
        unsigned v0 = (unsigned)__ldg(mi + tid);
        unsigned v1 = (unsigned)__ldg(mi + 32 + tid);
        int bad = __any_sync(FULLMASK, (v0 > 1u) || (v1 > 1u));
        if (tid == 0) g_mflag = bad;
    }

    if (idx < 768) {
        const float4* row;
        const float4* av;
        float* dst;
        if (idx < 576) {
            int s = idx / 192; int r = idx - s*192; int t = r >> 6; int d = r & 63;
            row = (const float4*)(W + (s*D + d)*D);
            av  = (const float4*)(a + t*128);
            dst = g_M1 + (s*3 + t)*64 + d;
        } else {
            int r = idx - 576; int t = r >> 6; int d = r & 63;
            row = (const float4*)(W + (t*D + d)*D);
            av  = (const float4*)(a + t*128 + 64);
            dst = g_w2 + t*64 + d;
        }
        float a0 = 0.f, a1 = 0.f, a2 = 0.f, a3 = 0.f;
        #pragma unroll
        for (int k = 0; k < 16; ++k) {
            float4 w = __ldg(row + k);
            float4 v = __ldg(av + k);
            a0 = fmaf(w.x, v.x, a0);
            a1 = fmaf(w.y, v.y, a1);
            a2 = fmaf(w.z, v.z, a2);
            a3 = fmaf(w.w, v.w, a3);
        }
        *dst = (a0 + a1) + (a2 + a3);
    }
}

// ================= main kernel: 128 threads, 2 batches/warp, 512 blocks =================
__global__ __launch_bounds__(128, 4) void hetgat_main(
    const float* __restrict__ h,      // (B, 22, 64)
    const void*  __restrict__ maskp,  // (3, B, 22)
    const float* __restrict__ W,      // (3, 64, 64) = rows k=t*64+d, h contiguous
    float* __restrict__ out,          // (B, 64)
    int B)
{
    __shared__ __align__(16) float s_c[4][96];       // per-warp coeffs c[t*32+node]
    __shared__ __align__(16) float s_g[4][2][192];   // per-warp, per-jb g[k]

    const int tid  = threadIdx.x;
    const int wid  = tid >> 5;
    const int lane = tid & 31;

    const bool u8m = (__ldg(&g_mflag) != 0);
    const int* mi32 = (const int*)maskp;
    const uint8_t* mu8 = (const uint8_t*)maskp;
    const size_t mT = (size_t)B * NN;

    // hoisted lane slices (batch-independent): lane owns d = 2*lane, 2*lane+1
    float w2x[3], w2y[3];
    #pragma unroll
    for (int t = 0; t < 3; ++t) {
        float2 v = __ldg(((const float2*)(g_w2 + t*64)) + lane);
        w2x[t] = v.x; w2y[t] = v.y;
    }
    float m1x[9], m1y[9];
    #pragma unroll
    for (int v = 0; v < 9; ++v) {
        float2 m = __ldg(((const float2*)(g_M1 + v*64)) + lane);
        m1x[v] = m.x; m1y[v] = m.y;
    }

    // per-lane pair mapping
    const int tA = lane / 10;            // 3 for lanes 30,31 (unused)
    const int nA = 1 + (lane - tA*10);
    const bool validA = (lane < 30);
    const int tO = lane / 11;
    const int nO = 11 + (lane - tO*11);

    const int bbase = blockIdx.x * 8 + wid * 2;

    #pragma unroll
    for (int jb = 0; jb < 2; ++jb) {
        const int b = bbase + jb;
        if (b < B) {   // warp-uniform
            const size_t boff = (size_t)b * NN;
            auto mld = [&](int t, int node) -> int {
                size_t i = (size_t)t * mT + boff + node;
                return u8m ? (int)mu8[i] : mi32[i];
            };
            // ---- prefetch masks (latency overlap with dots) ----
            int mAv = 1, mOv, mEv = 1, mSv = 0;
            if (validA)   mAv = mld(tA, nA);
            mOv = mld(tO, nO);
            if (lane == 30) mEv = mld(2, 21);
            if (lane < 3)   mSv = mld(lane, 0);

            // ---- load h ----
            const float2* hb = (const float2*)(h + (size_t)b * (NN*D));
            float hx[NN], hy[NN];
            #pragma unroll
            for (int n = 0; n < NN; ++n) {
                float2 v = hb[n*32 + lane];
                hx[n] = v.x; hy[n] = v.y;
            }

            // ======== PASS 1: ally dots (30) + opp pair (2,node21) in slot 30 ========
            float p[32];
            #pragma unroll
            for (int v = 0; v < 30; ++v) {
                int t = v / 10, n = 1 + v % 10;
                p[v] = fmaf(hy[n], w2y[t], hx[n] * w2x[t]);
            }
            p[30] = fmaf(hy[21], w2y[2], hx[21] * w2x[2]);
            p[31] = 0.f;
            #pragma unroll
            for (int sh = 16; sh >= 1; sh >>= 1) {
                bool up = (lane & sh) != 0;
                #pragma unroll
                for (int k = 0; k < sh; ++k) {
                    float send = up ? p[k] : p[k + sh];
                    float recv = __shfl_xor_sync(FULLMASK, send, sh);
                    float keep = up ? p[k + sh] : p[k];
                    p[k] = keep + recv;
                }
            }
            const float dA = p[0];   // lane v: ally dot v (lane30: opp(2,21))

            // ======== PASS 2: opp dots oi=0..31 ========
            #pragma unroll
            for (int v = 0; v < 32; ++v) {
                int t = v / 11, n = 11 + v % 11;
                p[v] = fmaf(hy[n], w2y[t], hx[n] * w2x[t]);
            }
            #pragma unroll
            for (int sh = 16; sh >= 1; sh >>= 1) {
                bool up = (lane & sh) != 0;
                #pragma unroll
                for (int k = 0; k < sh; ++k) {
                    float send = up ? p[k] : p[k + sh];
                    float recv = __shfl_xor_sync(FULLMASK, send, sh);
                    float keep = up ? p[k + sh] : p[k];
                    p[k] = keep + recv;
                }
            }
            const float dO = p[0];   // lane oi: opp dot oi

            // ======== PASS 3: self dots st[s*3+t] (9 in 16 slots) ========
            float q[16];
            #pragma unroll
            for (int v = 0; v < 9; ++v)
                q[v] = fmaf(hy[0], m1y[v], hx[0] * m1x[v]);
            #pragma unroll
            for (int v = 9; v < 16; ++v) q[v] = 0.f;
            #pragma unroll
            for (int sh = 8; sh >= 1; sh >>= 1) {
                bool up = (lane & sh) != 0;
                #pragma unroll
                for (int k = 0; k < sh; ++k) {
                    float send = up ? q[k] : q[k + sh];
                    float recv = __shfl_xor_sync(FULLMASK, send, sh);
                    float keep = up ? q[k + sh] : q[k];
                    q[k] = keep + recv;
                }
            }
            q[0] += __shfl_xor_sync(FULLMASK, q[0], 16);
            const float dX = q[0];   // lanes 0-8 hold st[s*3+t]

            // ======== softmax (no max-subtraction; shift-invariant, |e|<~12) ========
            float s0A = __shfl_sync(FULLMASK, dX, tA);
            float s1A = __shfl_sync(FULLMASK, dX, 3 + tA);
            float s2A = __shfl_sync(FULLMASK, dX, 6 + tA);
            float s0O = __shfl_sync(FULLMASK, dX, tO);
            float s1O = __shfl_sync(FULLMASK, dX, 3 + tO);
            float s2O = __shfl_sync(FULLMASK, dX, 6 + tO);

            float lsA = 0.f;
            if (validA && mAv == 0)
                lsA = __expf(s0A + dA) + __expf(s1A + dA) + __expf(s2A + dA);
            float lsO = 0.f;
            if (mOv == 0)
                lsO = __expf(s0O + dO) + __expf(s1O + dO) + __expf(s2O + dO);
            float lsE = 0.f;
            if (lane == 30 && mEv == 0)   // extra opp pair (t=2, node=21); lane30 tO==2
                lsE = __expf(s0O + dA) + __expf(s1O + dA) + __expf(s2O + dA);

            float SA = lsA, SO = lsO + lsE;
            #pragma unroll
            for (int off = 16; off > 0; off >>= 1) {
                SA += __shfl_xor_sync(FULLMASK, SA, off);
                SO += __shfl_xor_sync(FULLMASK, SO, off);
            }

            if (validA) s_c[wid][tA*32 + nA] = (mAv == 0) ? __fdividef(lsA, SA) : 0.f;
            s_c[wid][tO*32 + nO] = (mOv == 0) ? __fdividef(lsO, SO) : 0.f;
            if (lane == 30) s_c[wid][2*32 + 21] = (mEv == 0) ? __fdividef(lsE, SO) : 0.f;
            if (lane < 3)   s_c[wid][lane*32 + 0] = mSv ? 1.0f : 0.0f;
            __syncwarp();

            // ======== combine: g[t][d] = sum_n c[t][n]*h[n][d] ========
            float gx[3] = {0.f,0.f,0.f}, gy[3] = {0.f,0.f,0.f};
            const float4* scv = (const float4*)s_c[wid];
            #pragma unroll
            for (int t = 0; t < 3; ++t) {
                #pragma unroll
                for (int c4 = 0; c4 < 5; ++c4) {
                    float4 cq = scv[t*8 + c4];
                    int n0 = c4*4;
                    gx[t] = fmaf(cq.x, hx[n0+0], gx[t]); gy[t] = fmaf(cq.x, hy[n0+0], gy[t]);
                    gx[t] = fmaf(cq.y, hx[n0+1], gx[t]); gy[t] = fmaf(cq.y, hy[n0+1], gy[t]);
                    gx[t] = fmaf(cq.z, hx[n0+2], gx[t]); gy[t] = fmaf(cq.z, hy[n0+2], gy[t]);
                    gx[t] = fmaf(cq.w, hx[n0+3], gx[t]); gy[t] = fmaf(cq.w, hy[n0+3], gy[t]);
                }
                float4 cq = scv[t*8 + 5];   // nodes 20,21
                gx[t] = fmaf(cq.x, hx[20], gx[t]); gy[t] = fmaf(cq.x, hy[20], gy[t]);
                gx[t] = fmaf(cq.y, hx[21], gx[t]); gy[t] = fmaf(cq.y, hy[21], gy[t]);
            }
            #pragma unroll
            for (int t = 0; t < 3; ++t)
                ((float2*)(s_g[wid][jb] + t*64))[lane] = make_float2(gx[t], gy[t]);
            __syncwarp();
        }
    }

    // ======== final mat-vec: half-warp per batch, lane owns 4 h-columns ========
    const int half = lane >> 4;          // 0 -> jb0, 1 -> jb1
    const int hl   = lane & 15;          // h columns hl*4 .. hl*4+3
    const float4* gsrc = (const float4*)s_g[wid][half];
    const ulonglong2* Wv = (const ulonglong2*)W;   // row k at index k*16

    ull a0 = 0ull, a1 = 0ull;
    #pragma unroll 8
    for (int i = 0; i < 48; ++i) {       // k = 4i .. 4i+3
        float4 gv = gsrc[i];
        ulonglong2 w0 = __ldg(Wv + (4*i+0)*16 + hl);
        ulonglong2 w1 = __ldg(Wv + (4*i+1)*16 + hl);
        ulonglong2 w2 = __ldg(Wv + (4*i+2)*16 + hl);
        ulonglong2 w3 = __ldg(Wv + (4*i+3)*16 + hl);
        ull g0 = pack2(gv.x), g1 = pack2(gv.y), g2 = pack2(gv.z), g3 = pack2(gv.w);
        a0 = fma2(g0, w0.x, a0); a1 = fma2(g0, w0.y, a1);
        a0 = fma2(g1, w1.x, a0); a1 = fma2(g1, w1.y, a1);
        a0 = fma2(g2, w2.x, a0); a1 = fma2(g2, w2.y, a1);
        a0 = fma2(g3, w3.x, a0); a1 = fma2(g3, w3.y, a1);
    }

    const int bh = bbase + half;
    if (bh < B) {
        float r0 = lo32(a0), r1 = hi32(a0), r2 = lo32(a1), r3 = hi32(a1);
        float4 o;
        o.x = (r0 > 0.f) ? r0 : expm1f(r0);
        o.y = (r1 > 0.f) ? r1 : expm1f(r1);
        o.z = (r2 > 0.f) ? r2 : expm1f(r2);
        o.w = (r3 > 0.f) ? r3 : expm1f(r3);
        ((float4*)(out + (size_t)bh * D))[hl] = o;
    }
}

extern "C" void kernel_launch(void* const* d_in, const int* in_sizes, int n_in,
                              void* d_out, int out_size)
{
    const float* h = nullptr;
    const void* mask = nullptr;
    const float* W = nullptr;
    const float* a = nullptr;
    long hsz = 0; int hidx = -1;
    for (int i = 0; i < n_in; ++i) {
        if (in_sizes[i] == 12288)      W = (const float*)d_in[i];
        else if (in_sizes[i] == 384)   a = (const float*)d_in[i];
        if ((long)in_sizes[i] > hsz) { hsz = in_sizes[i]; hidx = i; }
    }
    h = (const float*)d_in[hidx];
    const int B = (int)(hsz / (NN * D));
    for (int i = 0; i < n_in; ++i) {
        if (i != hidx && (long)in_sizes[i] == (long)3 * B * NN)
            mask = d_in[i];
    }

    hetgat_prep<<<6, 128>>>(W, a, mask);
    dim3 grid((B + 7) / 8);   // 512 blocks for B=4096
    hetgat_main<<<grid, 128>>>(h, mask, W, (float*)d_out, B);
}